// round 1
// baseline (speedup 1.0000x reference)
#include <cuda_runtime.h>
#include <cstdint>

#define NN 50000
#define EE 600000
#define FF 128
#define HH 128
#define GG 500
#define CC 10
#define BN_EPS_F 1e-5f

// ---------------- scratch (device globals; no allocation allowed) ----------
__device__ int   g_is64;
__device__ float g_s1[NN * HH];     // scatter accum layer 1
__device__ float g_s2[NN * HH];     // scatter accum layer 2
__device__ float g_h1[NN * HH];     // h1 activations
__device__ float g_p [2 * GG * HH]; // p1 then p2 pooled

// ---------------- small helpers -------------------------------------------
__device__ __forceinline__ unsigned long long pack2(float lo, float hi) {
    unsigned long long r;
    asm("mov.b64 %0, {%1, %2};" : "=l"(r) : "f"(lo), "f"(hi));
    return r;
}
__device__ __forceinline__ float2 unpack2(unsigned long long v) {
    float2 r;
    asm("mov.b64 {%0, %1}, %2;" : "=f"(r.x), "=f"(r.y) : "l"(v));
    return r;
}
__device__ __forceinline__ void ffma2(unsigned long long& d,
                                      unsigned long long a,
                                      unsigned long long b) {
    asm("fma.rn.f32x2 %0, %1, %2, %0;" : "+l"(d) : "l"(a), "l"(b));
}
__device__ __forceinline__ void red_add_v4(float* p, float a, float b, float c, float d) {
    asm volatile("red.global.add.v4.f32 [%0], {%1,%2,%3,%4};"
                 :: "l"(p), "f"(a), "f"(b), "f"(c), "f"(d) : "memory");
}
__device__ __forceinline__ int load_index(const void* p, long long i, int is64) {
    return is64 ? (int)((const long long*)p)[i] : ((const int*)p)[i];
}

// ---------------- dtype detection -----------------------------------------
// If edge_index is int64, the high 32-bit word of every entry is 0 (values < N).
// If int32, odd 32-bit words are random indices in [0, 50000) — P(all 64 == 0) ~ 0.
__global__ void detect_kernel(const int* __restrict__ e) {
    if (blockIdx.x == 0 && threadIdx.x == 0) {
        int all0 = 1;
        for (int i = 0; i < 64; i++)
            if (e[2 * i + 1] != 0) { all0 = 0; break; }
        g_is64 = all0;
    }
}

// ---------------- zero scratch ---------------------------------------------
__global__ void zero_kernel() {
    int i = blockIdx.x * blockDim.x + threadIdx.x;
    float4 z = make_float4(0.f, 0.f, 0.f, 0.f);
    if (i < NN * HH / 4) { ((float4*)g_s1)[i] = z; ((float4*)g_s2)[i] = z; }
    if (i < 2 * GG * HH / 4) ((float4*)g_p)[i] = z;
}

// ---------------- edge scatter: sout[dst] += xin[src] ----------------------
// One warp per edge (grid-stride). 128 floats = 32 lanes x float4. Vectorized
// no-return L2 atomics (red.global.add.v4.f32).
__global__ void scatter_kernel(const void* __restrict__ eidx,
                               const float* __restrict__ xin_ext,
                               int which /*0: x->s1, 1: h1->s2*/) {
    const float* xin = which ? (const float*)g_h1 : xin_ext;
    float* sout = which ? g_s2 : g_s1;
    int lane = threadIdx.x & 31;
    int gwarp = (blockIdx.x * blockDim.x + threadIdx.x) >> 5;
    int nwarps = (gridDim.x * blockDim.x) >> 5;
    int is64 = g_is64;
    for (int e = gwarp; e < EE; e += nwarps) {
        int src, dst;
        if (is64) {
            src = (int)((const long long*)eidx)[e];
            dst = (int)((const long long*)eidx)[EE + e];
        } else {
            src = ((const int*)eidx)[e];
            dst = ((const int*)eidx)[EE + e];
        }
        float4 v = ((const float4*)(xin + (size_t)src * HH))[lane];
        float* d = sout + (size_t)dst * HH + lane * 4;
        red_add_v4(d, v.x, v.y, v.z, v.w);
    }
}

// ---------------- fused MLP: two 128x128 GEMMs + BN/ReLU + pooling ---------
// CONV==1: t = relu(BN(A@Wa + ba)); h = relu(t@Wb + bb); store h1, pool p1
// CONV==2: t = BN(relu(A@Wa + ba)); h = relu(t@Wb + bb); pool p2 only
// A = base + scat (self term fused into tile load).
// Block: 128 rows x 128 cols, K=128 fully smem-resident. fp32x2 packed FMA.
#define LDA 130
#define MLP_SMEM ((128 * LDA + 128 * 128) * 4)

template <int CONV>
__global__ void __launch_bounds__(256, 1)
mlp_kernel(const float* __restrict__ base_ext,
           const float* __restrict__ Wa, const float* __restrict__ ba,
           const float* __restrict__ bng, const float* __restrict__ bnb,
           const float* __restrict__ bnm, const float* __restrict__ bnv,
           const float* __restrict__ Wb, const float* __restrict__ bb,
           const void*  __restrict__ batch) {
    extern __shared__ float smem[];
    float* As = smem;             // [128][LDA] row-major (rows x K)
    float* Ws = smem + 128 * LDA; // [128][128]  (K x cols)

    const float* base = (CONV == 1) ? base_ext : (const float*)g_h1;
    const float* scat = (CONV == 1) ? (const float*)g_s1 : (const float*)g_s2;
    float* pool = (CONV == 1) ? g_p : (g_p + GG * HH);

    const int tid = threadIdx.x;
    const int ty = tid >> 4, tx = tid & 15;   // 16x16 threads, 8x8 micro-tile
    const int row0 = blockIdx.x * 128;
    const int cbase = tx * 8;

    // Load A tile = base + scat (guard tail rows with zeros)
    for (int i = tid; i < 128 * 32; i += 256) {
        int r = i >> 5, c4 = i & 31;
        int grow = row0 + r;
        float4 val = make_float4(0.f, 0.f, 0.f, 0.f);
        if (grow < NN) {
            float4 b = ((const float4*)(base + (size_t)grow * HH))[c4];
            float4 s = ((const float4*)(scat + (size_t)grow * HH))[c4];
            val = make_float4(b.x + s.x, b.y + s.y, b.z + s.z, b.w + s.w);
        }
        float* d = As + r * LDA + c4 * 4;
        d[0] = val.x; d[1] = val.y; d[2] = val.z; d[3] = val.w;
    }
    // Load Wa
    for (int i = tid; i < 128 * 32; i += 256)
        ((float4*)Ws)[i] = ((const float4*)Wa)[i];
    __syncthreads();

    // ---- GEMM 1 ----
    unsigned long long acc[8][4];
#pragma unroll
    for (int i = 0; i < 8; i++)
#pragma unroll
        for (int j = 0; j < 4; j++) acc[i][j] = 0ULL;

    const int arow = ty * 8;
#pragma unroll 8
    for (int k = 0; k < 128; ++k) {
        ulonglong2 wlo = ((const ulonglong2*)Ws)[k * 32 + tx * 2];
        ulonglong2 whi = ((const ulonglong2*)Ws)[k * 32 + tx * 2 + 1];
#pragma unroll
        for (int i = 0; i < 8; i++) {
            float a = As[(arow + i) * LDA + k];
            unsigned long long aa = pack2(a, a);
            ffma2(acc[i][0], aa, wlo.x);
            ffma2(acc[i][1], aa, wlo.y);
            ffma2(acc[i][2], aa, whi.x);
            ffma2(acc[i][3], aa, whi.y);
        }
    }

    // Column-wise epilogue params
    float sc[8], sh[8], bav[8];
#pragma unroll
    for (int j = 0; j < 8; j++) {
        int c = cbase + j;
        float s = bng[c] * rsqrtf(bnv[c] + BN_EPS_F);
        sc[j] = s;
        bav[j] = ba[c];
        if (CONV == 1) sh[j] = (ba[c] - bnm[c]) * s + bnb[c]; // t=max(acc*s+sh,0)
        else           sh[j] = bnb[c] - bnm[c] * s;           // t=max(acc+ba,0)*s+sh
    }

    __syncthreads();   // all GEMM1 smem reads done

    // Write intermediate T into As; reload Ws with Wb
#pragma unroll
    for (int i = 0; i < 8; i++) {
        int r = arow + i;
        float t[8];
#pragma unroll
        for (int j2 = 0; j2 < 4; j2++) {
            float2 u = unpack2(acc[i][j2]);
            t[2 * j2] = u.x; t[2 * j2 + 1] = u.y;
        }
#pragma unroll
        for (int j = 0; j < 8; j++) {
            float v;
            if (CONV == 1) v = fmaxf(t[j] * sc[j] + sh[j], 0.f);
            else           v = fmaxf(t[j] + bav[j], 0.f) * sc[j] + sh[j];
            As[r * LDA + cbase + j] = v;
        }
    }
    for (int i = tid; i < 128 * 32; i += 256)
        ((float4*)Ws)[i] = ((const float4*)Wb)[i];
    __syncthreads();

    // ---- GEMM 2 ----
#pragma unroll
    for (int i = 0; i < 8; i++)
#pragma unroll
        for (int j = 0; j < 4; j++) acc[i][j] = 0ULL;

#pragma unroll 8
    for (int k = 0; k < 128; ++k) {
        ulonglong2 wlo = ((const ulonglong2*)Ws)[k * 32 + tx * 2];
        ulonglong2 whi = ((const ulonglong2*)Ws)[k * 32 + tx * 2 + 1];
#pragma unroll
        for (int i = 0; i < 8; i++) {
            float a = As[(arow + i) * LDA + k];
            unsigned long long aa = pack2(a, a);
            ffma2(acc[i][0], aa, wlo.x);
            ffma2(acc[i][1], aa, wlo.y);
            ffma2(acc[i][2], aa, whi.x);
            ffma2(acc[i][3], aa, whi.y);
        }
    }

    // Epilogue 2: bias + relu; store h1 (CONV1) and pool
    float bb2[8];
#pragma unroll
    for (int j = 0; j < 8; j++) bb2[j] = bb[cbase + j];

    int is64 = g_is64;
#pragma unroll
    for (int i = 0; i < 8; i++) {
        int grow = row0 + arow + i;
        if (grow >= NN) continue;
        float t[8];
#pragma unroll
        for (int j2 = 0; j2 < 4; j2++) {
            float2 u = unpack2(acc[i][j2]);
            t[2 * j2]     = fmaxf(u.x + bb2[2 * j2], 0.f);
            t[2 * j2 + 1] = fmaxf(u.y + bb2[2 * j2 + 1], 0.f);
        }
        if (CONV == 1) {
            float4* hp = (float4*)(g_h1 + (size_t)grow * HH + cbase);
            hp[0] = make_float4(t[0], t[1], t[2], t[3]);
            hp[1] = make_float4(t[4], t[5], t[6], t[7]);
        }
        int b = load_index(batch, grow, is64);
        float* pp = pool + (size_t)b * HH + cbase;
        red_add_v4(pp,     t[0], t[1], t[2], t[3]);
        red_add_v4(pp + 4, t[4], t[5], t[6], t[7]);
    }
}

// ---------------- head: relu([p1,p2]@Wl1 + bl1) @ Wl2 + bl2 ----------------
// One warp per graph row; each lane owns 2 hidden units; Wl1 in smem.
#define HEAD_SMEM ((256 * 64 + 64 * CC + 64 + 16) * 4)

__global__ void __launch_bounds__(128)
head_kernel(const float* __restrict__ Wl1, const float* __restrict__ bl1,
            const float* __restrict__ Wl2, const float* __restrict__ bl2,
            float* __restrict__ out) {
    extern __shared__ float smem[];
    float* Wl1s = smem;                 // [256][64]
    float* Wl2s = smem + 256 * 64;      // [64][10]
    float* bl1s = Wl2s + 64 * CC;       // [64]
    float* bl2s = bl1s + 64;            // [10]

    int tid = threadIdx.x;
    for (int i = tid; i < 256 * 64 / 4; i += 128)
        ((float4*)Wl1s)[i] = ((const float4*)Wl1)[i];
    for (int i = tid; i < 64 * CC; i += 128) Wl2s[i] = Wl2[i];
    if (tid < 64) bl1s[tid] = bl1[tid];
    if (tid < CC) bl2s[tid] = bl2[tid];
    __syncthreads();

    int lane = tid & 31;
    int warp = tid >> 5;
    int r = blockIdx.x * 4 + warp;   // 125 blocks * 4 warps = 500 rows
    if (r >= GG) return;

    float h0 = bl1s[2 * lane], h1v = bl1s[2 * lane + 1];
    const float* row1 = g_p + (size_t)r * HH;
    const float* row2 = g_p + GG * HH + (size_t)r * HH;
#pragma unroll 4
    for (int k = 0; k < 128; ++k) {
        float v = row1[k];
        float2 w = ((const float2*)Wl1s)[k * 32 + lane];
        h0 += v * w.x; h1v += v * w.y;
    }
#pragma unroll 4
    for (int k = 0; k < 128; ++k) {
        float v = row2[k];
        float2 w = ((const float2*)Wl1s)[(128 + k) * 32 + lane];
        h0 += v * w.x; h1v += v * w.y;
    }
    h0 = fmaxf(h0, 0.f); h1v = fmaxf(h1v, 0.f);

#pragma unroll
    for (int c = 0; c < CC; c++) {
        float part = h0 * Wl2s[(2 * lane) * CC + c] + h1v * Wl2s[(2 * lane + 1) * CC + c];
#pragma unroll
        for (int off = 16; off; off >>= 1)
            part += __shfl_xor_sync(0xffffffffu, part, off);
        if (lane == 0) out[r * CC + c] = part + bl2s[c];
    }
}

// ---------------- launch ----------------------------------------------------
extern "C" void kernel_launch(void* const* d_in, const int* in_sizes, int n_in,
                              void* d_out, int out_size) {
    const float* x    = (const float*)d_in[0];
    const void*  eidx = d_in[1];
    const void*  batch= d_in[2];
    const float* W1a  = (const float*)d_in[3];
    const float* b1a  = (const float*)d_in[4];
    const float* g1   = (const float*)d_in[5];
    const float* be1  = (const float*)d_in[6];
    const float* m1   = (const float*)d_in[7];
    const float* v1   = (const float*)d_in[8];
    const float* W1b  = (const float*)d_in[9];
    const float* b1b  = (const float*)d_in[10];
    const float* W2a  = (const float*)d_in[11];
    const float* b2a  = (const float*)d_in[12];
    const float* g2   = (const float*)d_in[13];
    const float* be2  = (const float*)d_in[14];
    const float* m2   = (const float*)d_in[15];
    const float* v2   = (const float*)d_in[16];
    const float* W2b  = (const float*)d_in[17];
    const float* b2b  = (const float*)d_in[18];
    const float* Wl1  = (const float*)d_in[19];
    const float* bl1  = (const float*)d_in[20];
    const float* Wl2  = (const float*)d_in[21];
    const float* bl2  = (const float*)d_in[22];
    float* out = (float*)d_out;

    cudaFuncSetAttribute(mlp_kernel<1>, cudaFuncAttributeMaxDynamicSharedMemorySize, MLP_SMEM);
    cudaFuncSetAttribute(mlp_kernel<2>, cudaFuncAttributeMaxDynamicSharedMemorySize, MLP_SMEM);
    cudaFuncSetAttribute(head_kernel,   cudaFuncAttributeMaxDynamicSharedMemorySize, HEAD_SMEM);

    detect_kernel<<<1, 32>>>((const int*)eidx);
    zero_kernel<<<(NN * HH / 4 + 255) / 256, 256>>>();

    scatter_kernel<<<2368, 256>>>(eidx, x, 0);

    mlp_kernel<1><<<(NN + 127) / 128, 256, MLP_SMEM>>>(
        x, W1a, b1a, g1, be1, m1, v1, W1b, b1b, batch);

    scatter_kernel<<<2368, 256>>>(eidx, x /*unused*/, 1);

    mlp_kernel<2><<<(NN + 127) / 128, 256, MLP_SMEM>>>(
        x /*unused*/, W2a, b2a, g2, be2, m2, v2, W2b, b2b, batch);

    head_kernel<<<125, 128, HEAD_SMEM>>>(Wl1, bl1, Wl2, bl2, out);
}